// round 8
// baseline (speedup 1.0000x reference)
#include <cuda_runtime.h>
#include <cuda_bf16.h>
#include <cstdint>

#define NMAX 50000
#define EMAX 600000
#define D 128
#define ROWF 40   // floats per smem row (32 data in paired layout + 8 pad)

// ---------------- scratch (device globals; no runtime allocation) ------------
__device__ int   g_deg[4][NMAX];
__device__ int   g_rowptr[2][NMAX + 1];
__device__ int   g_cursor[2][NMAX];
__device__ int   g_col[2][EMAX];
__device__ int   g_bsum[2][256];
__device__ float g_srcscale[2][NMAX];
__device__ float g_Y0[(size_t)NMAX * D];
__device__ float g_Y1[(size_t)NMAX * D];
__device__ float g_hA[(size_t)NMAX * D];
__device__ float g_hB[(size_t)NMAX * D];
__device__ float g_Hcat[(size_t)NMAX * 2 * D];
__device__ float g_H1[(size_t)NMAX * D];
__device__ float g_stats[2 * D];
__device__ float g_aff[2 * D];

// ---------------- streams/events (created pre-main; no device-mem delta) -----
struct HxStreams {
    cudaStream_t sB{}, sC{};
    cudaEvent_t evStart{}, evBuild{}, evC{};
    HxStreams() {
        cudaStreamCreateWithFlags(&sB, cudaStreamNonBlocking);
        cudaStreamCreateWithFlags(&sC, cudaStreamNonBlocking);
        cudaEventCreateWithFlags(&evStart, cudaEventDisableTiming);
        cudaEventCreateWithFlags(&evBuild, cudaEventDisableTiming);
        cudaEventCreateWithFlags(&evC, cudaEventDisableTiming);
    }
};
static HxStreams g_hx;

// ---------------- tf32 helpers -----------------------------------------------
__device__ __forceinline__ unsigned f2tf32(float x) {
    unsigned u;
    asm("cvt.rna.tf32.f32 %0, %1;" : "=r"(u) : "f"(x));
    return u;
}
__device__ __forceinline__ void mma_tf32(float* d, unsigned a0, unsigned a1,
                                         unsigned a2, unsigned a3,
                                         unsigned b0, unsigned b1) {
    asm volatile(
        "mma.sync.aligned.m16n8k8.row.col.f32.tf32.tf32.f32 "
        "{%0,%1,%2,%3}, {%4,%5,%6,%7}, {%8,%9}, {%0,%1,%2,%3};"
        : "+f"(d[0]), "+f"(d[1]), "+f"(d[2]), "+f"(d[3])
        : "r"(a0), "r"(a1), "r"(a2), "r"(a3), "r"(b0), "r"(b1));
}
// paired layout: element (row, kloc) kloc in [0,32):
// pair p = (kloc>>3)*4 + (kloc&3) holds {k, k+4}; component = (kloc>>2)&1
__device__ __forceinline__ int pidx(int kloc) {
    return ((kloc >> 3) * 4 + (kloc & 3)) * 2 + ((kloc >> 2) & 1);
}

// ---------------- graph build ------------------------------------------------
__global__ void k_zero(int n) {
    int i = blockIdx.x * blockDim.x + threadIdx.x;
    if (i < n) {
        g_deg[0][i] = 0; g_deg[1][i] = 0; g_deg[2][i] = 0; g_deg[3][i] = 0;
    }
    if (i < 2 * D) g_stats[i] = 0.0f;
}

__global__ void k_deg2(const int* __restrict__ s0, const int* __restrict__ d0, int E0,
                       const int* __restrict__ s1, const int* __restrict__ d1, int E1) {
    int e = blockIdx.x * blockDim.x + threadIdx.x;
    if (e < E0) {
        atomicAdd(&g_deg[0][s0[e]], 1);
        atomicAdd(&g_deg[1][d0[e]], 1);
    }
    if (e < E1) {
        atomicAdd(&g_deg[2][s1[e]], 1);
        atomicAdd(&g_deg[3][d1[e]], 1);
    }
}

__global__ void k_scan1(int n) {
    int rel = blockIdx.y;
    int t = threadIdx.x;
    int i = blockIdx.x * 256 + t;
    int v = (i < n) ? g_deg[rel * 2 + 1][i] : 0;
#pragma unroll
    for (int o = 16; o > 0; o >>= 1) v += __shfl_down_sync(0xffffffffu, v, o);
    __shared__ int ws[8];
    if ((t & 31) == 0) ws[t >> 5] = v;
    __syncthreads();
    if (t == 0) {
        int s = 0;
#pragma unroll
        for (int j = 0; j < 8; ++j) s += ws[j];
        g_bsum[rel][blockIdx.x] = s;
    }
}

__global__ void k_scan2(int n) {
    int rel = blockIdx.y;
    int blk = blockIdx.x;
    int t = threadIdx.x;
    int lane = t & 31, wid = t >> 5;

    __shared__ int ws[8];
    __shared__ int s_off;
    __shared__ int wtot[8];

    int p = 0;
    for (int j = t; j < blk; j += 256) p += g_bsum[rel][j];
#pragma unroll
    for (int o = 16; o > 0; o >>= 1) p += __shfl_down_sync(0xffffffffu, p, o);
    if (lane == 0) ws[wid] = p;
    __syncthreads();
    if (t == 0) {
        int s = 0;
#pragma unroll
        for (int j = 0; j < 8; ++j) s += ws[j];
        s_off = s;
    }
    __syncthreads();
    int offset = s_off;

    int i = blk * 256 + t;
    int v = (i < n) ? g_deg[rel * 2 + 1][i] : 0;
    int x = v;
#pragma unroll
    for (int o = 1; o < 32; o <<= 1) {
        int y = __shfl_up_sync(0xffffffffu, x, o);
        if (lane >= o) x += y;
    }
    if (lane == 31) wtot[wid] = x;
    __syncthreads();
    int add = 0;
#pragma unroll
    for (int j = 0; j < 8; ++j) add += (j < wid) ? wtot[j] : 0;
    int incl = x + add;

    if (i < n) {
        int start = offset + incl - v;
        g_rowptr[rel][i] = start;
        g_cursor[rel][i] = start;
        int od = g_deg[rel * 2][i];
        g_srcscale[rel][i] = rsqrtf((float)(od > 0 ? od : 1));
        if (i == n - 1) g_rowptr[rel][n] = offset + incl;
    }
}

__global__ void k_fill2(const int* __restrict__ s0, const int* __restrict__ d0, int E0,
                        const int* __restrict__ s1, const int* __restrict__ d1, int E1) {
    int e = blockIdx.x * blockDim.x + threadIdx.x;
    if (e < E0) {
        int p = atomicAdd(&g_cursor[0][d0[e]], 1);
        g_col[0][p] = s0[e];
    }
    if (e < E1) {
        int p = atomicAdd(&g_cursor[1][d1[e]], 1);
        g_col[1][p] = s1[e];
    }
}

// ---------------- aggregation ------------------------------------------------
__global__ void k_agg(const float* __restrict__ Y, int rel,
                      const float* __restrict__ bias, float* __restrict__ out,
                      int n, int ldc, int relu) {
    int warp = (blockIdx.x * blockDim.x + threadIdx.x) >> 5;
    int lane = threadIdx.x & 31;
    if (warp >= n) return;
    const int* __restrict__ rowptr = g_rowptr[rel];
    const int* __restrict__ col = g_col[rel];
    const float* __restrict__ ss = g_srcscale[rel];
    int s = rowptr[warp], e = rowptr[warp + 1];
    float4 acc = make_float4(0.f, 0.f, 0.f, 0.f);
    const float4* Y4 = (const float4*)Y;
    for (int i = s; i < e; ++i) {
        int src = __ldg(col + i);
        float w = __ldg(ss + src);
        float4 v = __ldg(Y4 + (size_t)src * 32 + lane);
        acc.x += w * v.x; acc.y += w * v.y; acc.z += w * v.z; acc.w += w * v.w;
    }
    int deg = e - s;
    float sc = rsqrtf((float)(deg > 0 ? deg : 1));
    float4 b = ((const float4*)bias)[lane];
    acc.x = acc.x * sc + b.x;
    acc.y = acc.y * sc + b.y;
    acc.z = acc.z * sc + b.z;
    acc.w = acc.w * sc + b.w;
    if (relu) {
        acc.x = fmaxf(acc.x, 0.f); acc.y = fmaxf(acc.y, 0.f);
        acc.z = fmaxf(acc.z, 0.f); acc.w = fmaxf(acc.w, 0.f);
    }
    *(float4*)(out + (size_t)warp * ldc + lane * 4) = acc;
}

// ---------------- TF32 tensor-core GEMM: C[M,128] = A[M,K] @ W[K,128] ---------
// block: 256 thr = 8 warps; warp tile 16x128; K-tiles of 32; mma.m16n8k8 tf32.
__global__ __launch_bounds__(256) void k_gemm(const float* __restrict__ A,
                                              const float* __restrict__ W,
                                              float* __restrict__ C,
                                              int M, int K, int lda, int ldc) {
    __shared__ unsigned As[128 * ROWF];   // [row][paired k]
    __shared__ unsigned Bs[128 * ROWF];   // [n][paired k]
    int tid = threadIdx.x;
    int wid = tid >> 5, lane = tid & 31;
    int g = lane >> 2, tig = lane & 3;
    int rowBase = blockIdx.x * 128;
    int warpM = wid * 16;

    float acc[16][4];
#pragma unroll
    for (int i = 0; i < 16; ++i)
#pragma unroll
        for (int j = 0; j < 4; ++j) acc[i][j] = 0.f;

    for (int k0 = 0; k0 < K; k0 += 32) {
        // A tile: 128 rows x 32 k = 1024 float4; 4 per thread
#pragma unroll
        for (int i = 0; i < 4; ++i) {
            int f4 = tid + i * 256;
            int r = f4 >> 3;
            int kc = (f4 & 7) << 2;
            int gm = rowBase + r;
            float4 v = make_float4(0.f, 0.f, 0.f, 0.f);
            if (gm < M) v = *(const float4*)(A + (size_t)gm * lda + k0 + kc);
            unsigned* dst = &As[r * ROWF];
            dst[pidx(kc + 0)] = f2tf32(v.x);
            dst[pidx(kc + 1)] = f2tf32(v.y);
            dst[pidx(kc + 2)] = f2tf32(v.z);
            dst[pidx(kc + 3)] = f2tf32(v.w);
        }
        // B tile: 32 k-rows x 128 n = 1024 float4; transpose to Bs[n][k]
#pragma unroll
        for (int i = 0; i < 4; ++i) {
            int f4 = tid + i * 256;
            int kr = f4 >> 5;
            int nc = (f4 & 31) << 2;
            float4 v = *(const float4*)(W + (size_t)(k0 + kr) * 128 + nc);
            int pk = pidx(kr);
            Bs[(nc + 0) * ROWF + pk] = f2tf32(v.x);
            Bs[(nc + 1) * ROWF + pk] = f2tf32(v.y);
            Bs[(nc + 2) * ROWF + pk] = f2tf32(v.z);
            Bs[(nc + 3) * ROWF + pk] = f2tf32(v.w);
        }
        __syncthreads();
#pragma unroll
        for (int kkIdx = 0; kkIdx < 4; ++kkIdx) {
            int po = (kkIdx * 4 + tig) * 2;
            uint2 a02 = *(const uint2*)&As[(warpM + g) * ROWF + po];
            uint2 a13 = *(const uint2*)&As[(warpM + g + 8) * ROWF + po];
#pragma unroll
            for (int nf = 0; nf < 16; ++nf) {
                uint2 b01 = *(const uint2*)&Bs[(nf * 8 + g) * ROWF + po];
                mma_tf32(acc[nf], a02.x, a13.x, a02.y, a13.y, b01.x, b01.y);
            }
        }
        __syncthreads();
    }

    int row0 = rowBase + warpM + g;
    int row1 = row0 + 8;
#pragma unroll
    for (int nf = 0; nf < 16; ++nf) {
        int colb = nf * 8 + tig * 2;
        if (row0 < M) *(float2*)(C + (size_t)row0 * ldc + colb) =
            make_float2(acc[nf][0], acc[nf][1]);
        if (row1 < M) *(float2*)(C + (size_t)row1 * ldc + colb) =
            make_float2(acc[nf][2], acc[nf][3]);
    }
}

// ---------------- BN stats / finalize / fused head ---------------------------
__global__ void k_bnstats(const float* __restrict__ H, int M) {
    int c = threadIdx.x;
    int rows_per_block = (M + gridDim.x - 1) / gridDim.x;
    int r0 = blockIdx.x * rows_per_block;
    int r1 = r0 + rows_per_block; if (r1 > M) r1 = M;
    float s = 0.f, q = 0.f;
    for (int r = r0; r < r1; ++r) {
        float v = H[(size_t)r * D + c];
        s += v; q += v * v;
    }
    atomicAdd(&g_stats[c], s);
    atomicAdd(&g_stats[D + c], q);
}

__global__ void k_bnfinal(const float* __restrict__ gamma,
                          const float* __restrict__ beta, int M) {
    int c = threadIdx.x;
    float invM = 1.0f / (float)M;
    float mu = g_stats[c] * invM;
    float var = g_stats[D + c] * invM - mu * mu;
    float a = gamma[c] * rsqrtf(var + 1e-5f);
    g_aff[c] = a;
    g_aff[D + c] = beta[c] - mu * a;
}

__global__ void k_head(const float* __restrict__ H, const float* __restrict__ Wm2,
                       float* __restrict__ out, int n) {
    int warp = (blockIdx.x * blockDim.x + threadIdx.x) >> 5;
    int lane = threadIdx.x & 31;
    if (warp >= n) return;
    float4 h = ((const float4*)(H + (size_t)warp * D))[lane];
    float4 a = ((const float4*)g_aff)[lane];
    float4 b = ((const float4*)(g_aff + D))[lane];
    float v0 = fmaxf(h.x * a.x + b.x, 0.f);
    float v1 = fmaxf(h.y * a.y + b.y, 0.f);
    float v2 = fmaxf(h.z * a.z + b.z, 0.f);
    float v3 = fmaxf(h.w * a.w + b.w, 0.f);
    float4 wA = __ldg((const float4*)Wm2 + lane * 2 + 0);
    float4 wB = __ldg((const float4*)Wm2 + lane * 2 + 1);
    float s0 = v0 * wA.x + v1 * wA.z + v2 * wB.x + v3 * wB.z;
    float s1 = v0 * wA.y + v1 * wA.w + v2 * wB.y + v3 * wB.w;
#pragma unroll
    for (int off = 16; off > 0; off >>= 1) {
        s0 += __shfl_down_sync(0xffffffffu, s0, off);
        s1 += __shfl_down_sync(0xffffffffu, s1, off);
    }
    if (lane == 0) {
        out[(size_t)warp * 2 + 0] = s0;
        out[(size_t)warp * 2 + 1] = s1;
    }
}

// ---------------- launch -----------------------------------------------------
extern "C" void kernel_launch(void* const* d_in, const int* in_sizes, int n_in,
                              void* d_out, int out_size) {
    const float* xA   = (const float*)d_in[0];
    const float* xB   = (const float*)d_in[1];
    const int* src0   = (const int*)d_in[2];
    const int* dst0   = (const int*)d_in[3];
    const int* src1   = (const int*)d_in[4];
    const int* dst1   = (const int*)d_in[5];
    const float* W1_0 = (const float*)d_in[6];
    const float* b1_0 = (const float*)d_in[7];
    const float* W1_1 = (const float*)d_in[8];
    const float* b1_1 = (const float*)d_in[9];
    const float* W2_0 = (const float*)d_in[10];
    const float* b2_0 = (const float*)d_in[11];
    const float* W2_1 = (const float*)d_in[12];
    const float* b2_1 = (const float*)d_in[13];
    const float* Wm1  = (const float*)d_in[14];
    const float* gamma= (const float*)d_in[15];
    const float* beta = (const float*)d_in[16];
    const float* Wm2  = (const float*)d_in[17];
    float* out = (float*)d_out;

    int n  = in_sizes[0] / D;
    int E0 = in_sizes[2];
    int E1 = in_sizes[4];
    int Emax = E0 > E1 ? E0 : E1;

    float *pY0, *pY1, *phA, *phB, *pHcat, *pH1;
    cudaGetSymbolAddress((void**)&pY0, g_Y0);
    cudaGetSymbolAddress((void**)&pY1, g_Y1);
    cudaGetSymbolAddress((void**)&phA, g_hA);
    cudaGetSymbolAddress((void**)&phB, g_hB);
    cudaGetSymbolAddress((void**)&pHcat, g_Hcat);
    cudaGetSymbolAddress((void**)&pH1, g_H1);

    int gbE = (Emax + 255) / 256;
    int gbN = (n + 255) / 256;
    int gbW = (n + 7) / 8;
    int gbG = (n + 127) / 128;
    int scanBlocks = (n + 255) / 256;

    cudaStream_t s0 = 0;
    cudaStream_t sB = g_hx.sB, sC = g_hx.sC;

    // fork
    cudaEventRecord(g_hx.evStart, s0);
    cudaStreamWaitEvent(sB, g_hx.evStart, 0);
    cudaStreamWaitEvent(sC, g_hx.evStart, 0);

    // graph build on sB (overlaps with conv1 GEMMs)
    k_zero<<<gbN, 256, 0, sB>>>(n);
    k_deg2<<<gbE, 256, 0, sB>>>(src0, dst0, E0, src1, dst1, E1);
    k_scan1<<<dim3(scanBlocks, 2), 256, 0, sB>>>(n);
    k_scan2<<<dim3(scanBlocks, 2), 256, 0, sB>>>(n);
    k_fill2<<<gbE, 256, 0, sB>>>(src0, dst0, E0, src1, dst1, E1);
    cudaEventRecord(g_hx.evBuild, sB);

    // chain A on s0
    k_gemm<<<gbG, 256, 0, s0>>>(xA, W1_0, pY0, n, 128, 128, 128);
    cudaStreamWaitEvent(s0, g_hx.evBuild, 0);
    k_agg<<<gbW, 256, 0, s0>>>(pY0, 0, b1_0, phB, n, 128, 1);
    k_gemm<<<gbG, 256, 0, s0>>>(phB, W2_1, pY0, n, 128, 128, 128);
    k_agg<<<gbW, 256, 0, s0>>>(pY0, 1, b2_1, pHcat, n, 256, 0);

    // chain B on sC
    k_gemm<<<gbG, 256, 0, sC>>>(xB, W1_1, pY1, n, 128, 128, 128);
    cudaStreamWaitEvent(sC, g_hx.evBuild, 0);
    k_agg<<<gbW, 256, 0, sC>>>(pY1, 1, b1_1, phA, n, 128, 1);
    k_gemm<<<gbG, 256, 0, sC>>>(phA, W2_0, pY1, n, 128, 128, 128);
    k_agg<<<gbW, 256, 0, sC>>>(pY1, 0, b2_0, pHcat + 128, n, 256, 0);
    cudaEventRecord(g_hx.evC, sC);

    // join + MLP head on s0
    cudaStreamWaitEvent(s0, g_hx.evC, 0);
    k_gemm<<<gbG, 256, 0, s0>>>(pHcat, Wm1, pH1, n, 256, 256, 128);
    k_bnstats<<<256, 128, 0, s0>>>(pH1, n);
    k_bnfinal<<<1, 128, 0, s0>>>(gamma, beta, n);
    k_head<<<gbW, 256, 0, s0>>>(pH1, Wm2, out, n);
}